// round 1
// baseline (speedup 1.0000x reference)
#include <cuda_runtime.h>

#define NQ      10
#define NLAYERS 5
#define NOUT    4

// ---------- complex helpers ----------
__device__ __forceinline__ void cfma(float2& acc, float2 u, float2 v) {
    acc.x = fmaf(u.x, v.x, fmaf(-u.y, v.y, acc.x));
    acc.y = fmaf(u.x, v.y, fmaf( u.y, v.x, acc.y));
}

struct Gate { float2 u00, u01, u10, u11; };

// Fused  U = RY(phi) * RZ(theta) * RY(alpha)
// u00 = ( cosP*ct, -cosM*st)   u01 = (-sinP*ct, -sinM*st)
// u10 = ( sinP*ct, -sinM*st)   u11 = ( cosP*ct,  cosM*st)
// where P=(phi+alpha)/2, M=(phi-alpha)/2, ct/st = cos/sin(theta/2)
__device__ __forceinline__ Gate make_gate(float alpha, float theta, float phi) {
    float sp, cp, sm, cm, st, ct;
    __sincosf(0.5f * (phi + alpha), &sp, &cp);
    __sincosf(0.5f * (phi - alpha), &sm, &cm);
    __sincosf(0.5f * theta,        &st, &ct);
    Gate g;
    g.u00 = make_float2( cp * ct, -cm * st);
    g.u01 = make_float2(-sp * ct, -sm * st);
    g.u10 = make_float2( sp * ct, -sm * st);
    g.u11 = make_float2( cp * ct,  cm * st);
    return g;
}

// ---------- single-qubit gate on a register-local bit (qubits 0..4) ----------
template<int MASK>
__device__ __forceinline__ void gate_local(float2* s, Gate g) {
#pragma unroll
    for (int j = 0; j < 32; j++) {
        if ((j & MASK) == 0) {
            float2 a = s[j], b = s[j + MASK];
            float2 na = make_float2(0.f, 0.f);
            float2 nb = make_float2(0.f, 0.f);
            cfma(na, g.u00, a); cfma(na, g.u01, b);
            cfma(nb, g.u10, a); cfma(nb, g.u11, b);
            s[j] = na; s[j + MASK] = nb;
        }
    }
}

// ---------- single-qubit gate on a lane bit (qubits 5..9) ----------
template<int LMASK>
__device__ __forceinline__ void gate_cross(float2* s, int lane, Gate g) {
    bool hi = (lane & LMASK) != 0;
    float2 ua = hi ? g.u11 : g.u00;  // coeff for own amplitude
    float2 ub = hi ? g.u10 : g.u01;  // coeff for partner amplitude
#pragma unroll
    for (int j = 0; j < 32; j++) {
        float2 p;
        p.x = __shfl_xor_sync(0xffffffffu, s[j].x, LMASK);
        p.y = __shfl_xor_sync(0xffffffffu, s[j].y, LMASK);
        float2 n = make_float2(0.f, 0.f);
        cfma(n, ua, s[j]);
        cfma(n, ub, p);
        s[j] = n;
    }
}

// compile-time loop over qubits (fused gate per qubit)
template<int Q>
__device__ __forceinline__ void apply_sq_gates(float2* s, int lane, const float* xv,
                                               const float* iscL, const float* wL) {
    if constexpr (Q < NQ) {
        float xq    = xv[Q];
        float alpha = iscL[Q] * xq;
        float theta = fmaf(iscL[Q + NQ], xq, wL[Q]);
        float phi   = wL[Q + NQ];
        Gate g = make_gate(alpha, theta, phi);
        if constexpr (Q < 5) gate_local<(1 << Q)>(s, g);
        else                 gate_cross<(1 << (Q - 5))>(s, lane, g);
        apply_sq_gates<Q + 1>(s, lane, xv, iscL, wL);
    }
}

// ---------- CNOTs ----------
// both bits local: pure register permutation
template<int CB, int TB>
__device__ __forceinline__ void cnot_ll(float2* s) {
#pragma unroll
    for (int j = 0; j < 32; j++) {
        if ((j & (1 << CB)) && !(j & (1 << TB))) {
            float2 t = s[j];
            s[j] = s[j ^ (1 << TB)];
            s[j ^ (1 << TB)] = t;
        }
    }
}

// both bits on lanes: shuffle, take if control lane-bit set
template<int CLM, int TLM>
__device__ __forceinline__ void cnot_cc(float2* s, int lane) {
    bool ctrl = (lane & CLM) != 0;
#pragma unroll
    for (int j = 0; j < 32; j++) {
        float px = __shfl_xor_sync(0xffffffffu, s[j].x, TLM);
        float py = __shfl_xor_sync(0xffffffffu, s[j].y, TLM);
        if (ctrl) { s[j].x = px; s[j].y = py; }
    }
}

__device__ __forceinline__ void cnot_ring(float2* s, int lane) {
    // CNOT(0,1) .. CNOT(3,4): local-local
    cnot_ll<0, 1>(s);
    cnot_ll<1, 2>(s);
    cnot_ll<2, 3>(s);
    cnot_ll<3, 4>(s);
    // CNOT(4,5): control = local bit 4, target = lane bit 0.
    // All amplitudes with local bit4=1 swap with lane^1 (unconditional exchange).
#pragma unroll
    for (int j = 16; j < 32; j++) {
        s[j].x = __shfl_xor_sync(0xffffffffu, s[j].x, 1);
        s[j].y = __shfl_xor_sync(0xffffffffu, s[j].y, 1);
    }
    // CNOT(5,6)..(8,9): lane-lane
    cnot_cc<1, 2>(s, lane);
    cnot_cc<2, 4>(s, lane);
    cnot_cc<4, 8>(s, lane);
    cnot_cc<8, 16>(s, lane);
    // CNOT(9,0): control = lane bit 4, target = local bit 0 -> predicated local swap
    {
        bool ctrl = (lane & 16) != 0;
#pragma unroll
        for (int j = 0; j < 32; j += 2) {
            float2 a = s[j], b = s[j + 1];
            s[j]     = ctrl ? b : a;
            s[j + 1] = ctrl ? a : b;
        }
    }
}

// ---------- main kernel: one warp = one batch sample ----------
__global__ void __launch_bounds__(256)
qsim_kernel(const float* __restrict__ x, const float* __restrict__ isc,
            const float* __restrict__ w, const float* __restrict__ oscale,
            float* __restrict__ out, int batch) {
    int gw   = (blockIdx.x * blockDim.x + threadIdx.x) >> 5;
    int lane = threadIdx.x & 31;
    if (gw >= batch) return;

    float xv[NQ];
#pragma unroll
    for (int i = 0; i < NQ; i++) xv[i] = x[gw * NQ + i];

    // state: amplitude index = lane*32 + j ; qubit k <-> bit k (bits 0-4 local, 5-9 lane)
    float2 s[32];
#pragma unroll
    for (int j = 0; j < 32; j++) s[j] = make_float2(0.f, 0.f);
    s[0].x = (lane == 0) ? 1.0f : 0.0f;   // |0...0>

#pragma unroll 1
    for (int layer = 0; layer < NLAYERS; layer++) {
        const float* iscL = isc + layer * 2 * NQ;
        const float* wL   = w   + layer * 2 * NQ;
        apply_sq_gates<0>(s, lane, xv, iscL, wL);
        cnot_ring(s, lane);
    }

    // <Z_i> for qubits 0..3 (all local bits)
    float acc0 = 0.f, acc1 = 0.f, acc2 = 0.f, acc3 = 0.f;
#pragma unroll
    for (int j = 0; j < 32; j++) {
        float p = fmaf(s[j].x, s[j].x, s[j].y * s[j].y);
        acc0 += (j & 1) ? -p : p;
        acc1 += (j & 2) ? -p : p;
        acc2 += (j & 4) ? -p : p;
        acc3 += (j & 8) ? -p : p;
    }
#pragma unroll
    for (int o = 16; o; o >>= 1) {
        acc0 += __shfl_xor_sync(0xffffffffu, acc0, o);
        acc1 += __shfl_xor_sync(0xffffffffu, acc1, o);
        acc2 += __shfl_xor_sync(0xffffffffu, acc2, o);
        acc3 += __shfl_xor_sync(0xffffffffu, acc3, o);
    }
    if (lane == 0) {
        float4 r = make_float4(acc0 * oscale[0], acc1 * oscale[1],
                               acc2 * oscale[2], acc3 * oscale[3]);
        *reinterpret_cast<float4*>(out + gw * 4) = r;
    }
}

extern "C" void kernel_launch(void* const* d_in, const int* in_sizes, int n_in,
                              void* d_out, int out_size) {
    const float* x    = (const float*)d_in[0];  // (B, 10)
    const float* isc  = (const float*)d_in[1];  // (5, 20)
    const float* w    = (const float*)d_in[2];  // (5, 20)
    const float* oscl = (const float*)d_in[3];  // (4,)
    float*       out  = (float*)d_out;          // (B, 4)

    int batch   = in_sizes[0] / NQ;             // 4096
    int threads = 256;                          // 8 warps = 8 samples / block
    int blocks  = (batch * 32 + threads - 1) / threads;
    qsim_kernel<<<blocks, threads>>>(x, isc, w, oscl, out, batch);
}